// round 12
// baseline (speedup 1.0000x reference)
#include <cuda_runtime.h>
#include <cuda_bf16.h>
#include <math.h>
#include <stdint.h>

#define H        128
#define NC       10
#define NATT     3
#define B_TOTAL  16384
#define M_ROWS   128
#define THREADS  512
#define KT       8
#define KT2      4
#define EPS_LN   1e-5f
#define SBB      272
#define SBW      272

typedef unsigned long long ull;

// ---------------- smem byte layout ----------------
#define O_AHI  0
#define O_ALO  (O_AHI + 128 * SBB)
#define O_WHI  (O_ALO + 128 * SBB)
#define O_WLO  (O_WHI + 128 * SBW)
#define O_PART (O_WLO + 128 * SBW)
#define PART_STRIDE 68
#define O_FIN  (O_PART + 128 * PART_STRIDE * 4)
#define FIN_STRIDE 20
#define O_LN   (O_FIN + 128 * FIN_STRIDE * 4)
#define LN_STRIDE 12
#define O_VEC  (O_LN + 128 * LN_STRIDE * 4)
#define VF_BIAS 0
#define VF_G    (VF_BIAS + 4 * 128)
#define VF_BE   (VF_G + 3 * 128)
#define VF_WC   (VF_BE + 3 * 128)
#define VF_BC   (VF_WC + H * NC)
#define VF_TOT  (VF_BC + 16)
#define SMEM_TOTAL (O_VEC + VF_TOT * 4)

// ---------------- f32x2 helpers ----------------
__device__ __forceinline__ ull pack2(float lo, float hi) {
    ull r; asm("mov.b64 %0, {%1, %2};" : "=l"(r) : "f"(lo), "f"(hi)); return r;
}
__device__ __forceinline__ void unpack2(ull v, float& lo, float& hi) {
    asm("mov.b64 {%0, %1}, %2;" : "=f"(lo), "=f"(hi) : "l"(v));
}
__device__ __forceinline__ ull fma2(ull a, ull b, ull c) {
    ull d; asm("fma.rn.f32x2 %0, %1, %2, %3;" : "=l"(d) : "l"(a), "l"(b), "l"(c)); return d;
}
__device__ __forceinline__ ull add2(ull a, ull b) {
    ull d; asm("add.rn.f32x2 %0, %1, %2;" : "=l"(d) : "l"(a), "l"(b)); return d;
}
__device__ __forceinline__ ull mul2(ull a, ull b) {
    ull d; asm("mul.rn.f32x2 %0, %1, %2;" : "=l"(d) : "l"(a), "l"(b)); return d;
}

__device__ __forceinline__ uint32_t smem_u32(const void* p) {
    uint32_t a;
    asm("{ .reg .u64 t; cvta.to.shared.u64 t, %1; cvt.u32.u64 %0, t; }" : "=r"(a) : "l"(p));
    return a;
}

// ---------------- tensor-core primitives ----------------
#define LDSM4(r, addr)                                                          \
    asm volatile("ldmatrix.sync.aligned.m8n8.x4.shared.b16 {%0,%1,%2,%3}, [%4];" \
        : "=r"((r)[0]), "=r"((r)[1]), "=r"((r)[2]), "=r"((r)[3]) : "r"(addr))
#define LDSM4T(r, addr)                                                         \
    asm volatile("ldmatrix.sync.aligned.m8n8.x4.trans.shared.b16 {%0,%1,%2,%3}, [%4];" \
        : "=r"((r)[0]), "=r"((r)[1]), "=r"((r)[2]), "=r"((r)[3]) : "r"(addr))

#define MMA_BF16(d, a, b0, b1)                                                  \
    asm volatile("mma.sync.aligned.m16n8k16.row.col.f32.bf16.bf16.f32 "         \
        "{%0,%1,%2,%3}, {%4,%5,%6,%7}, {%8,%9}, {%0,%1,%2,%3};"                 \
        : "+f"((d)[0]), "+f"((d)[1]), "+f"((d)[2]), "+f"((d)[3])                \
        : "r"((a)[0]), "r"((a)[1]), "r"((a)[2]), "r"((a)[3]), "r"(b0), "r"(b1))

#define BARG(g) asm volatile("bar.sync %0, %1;" :: "r"((g) + 1), "r"(128) : "memory")

// ---------------- bf16 split/join ----------------
union BU { __nv_bfloat162 b; uint32_t u; };
__device__ __forceinline__ void split2(float v0, float v1, uint32_t& hi2, uint32_t& lo2) {
    BU h; h.b = __floats2bfloat162_rn(v0, v1);
    float r0 = v0 - __bfloat162float(__low2bfloat16(h.b));
    float r1 = v1 - __bfloat162float(__high2bfloat16(h.b));
    BU l; l.b = __floats2bfloat162_rn(r0, r1);
    hi2 = h.u; lo2 = l.u;
}
__device__ __forceinline__ float2 join2(uint32_t hi2, uint32_t lo2) {
    BU a, b; a.u = hi2; b.u = lo2;
    float2 r;
    r.x = __bfloat162float(__low2bfloat16(a.b))  + __bfloat162float(__low2bfloat16(b.b));
    r.y = __bfloat162float(__high2bfloat16(a.b)) + __bfloat162float(__high2bfloat16(b.b));
    return r;
}

__device__ __forceinline__ float fast_tanh(float x) {
    return 1.0f - 2.0f * __fdividef(1.0f, __expf(2.0f * x) + 1.0f);
}

__device__ __forceinline__ void mom_acc(ull sm2[KT2], ull mm2[KT2], float u, float h) {
    float uu = u * u;
    ull pwp = pack2(1.0f, u);
    ull u2d = pack2(uu, uu);
    ull h2  = pack2(h, h);
#pragma unroll
    for (int p = 0; p < KT2; p++) {
        sm2[p] = add2(sm2[p], pwp);
        mm2[p] = fma2(pwp, h2, mm2[p]);
        if (p < KT2 - 1) pwp = mul2(pwp, u2d);
    }
}

// 3-pass bf16-split GEMM. A tile m-major (non-trans LDSM); W tile k-major (trans LDSM).
__device__ __forceinline__ void mma_gemm(uint32_t sb, uint32_t aOff, uint32_t bOffT,
                                         float d[2][4][4]) {
#pragma unroll
    for (int mi = 0; mi < 2; mi++)
#pragma unroll
        for (int na = 0; na < 4; na++)
#pragma unroll
            for (int e = 0; e < 4; e++) d[mi][na][e] = 0.f;

    const uint32_t aHi = sb + O_AHI + aOff, aLo = sb + O_ALO + aOff;
    const uint32_t bHi = sb + O_WHI + bOffT, bLo = sb + O_WLO + bOffT;
#pragma unroll
    for (int kk = 0; kk < 8; kk++) {
        uint32_t ko  = kk * 32;
        uint32_t bko = kk * 16 * SBW;
        uint32_t ahi0[4], ahi1[4], alo0[4], alo1[4];
        uint32_t bhi0[4], bhi1[4], blo0[4], blo1[4];
        LDSM4(ahi0, aHi + ko);
        LDSM4(ahi1, aHi + 16 * SBB + ko);
        LDSM4(alo0, aLo + ko);
        LDSM4(alo1, aLo + 16 * SBB + ko);
        LDSM4T(bhi0, bHi + bko);
        LDSM4T(bhi1, bHi + bko + 32);
        LDSM4T(blo0, bLo + bko);
        LDSM4T(blo1, bLo + bko + 32);
#pragma unroll
        for (int mi = 0; mi < 2; mi++) {
            uint32_t* ah = mi ? ahi1 : ahi0;
            uint32_t* al = mi ? alo1 : alo0;
#pragma unroll
            for (int np = 0; np < 2; np++) {
                uint32_t* bh = np ? bhi1 : bhi0;
                uint32_t* bl = np ? blo1 : blo0;
#pragma unroll
                for (int ns = 0; ns < 2; ns++) {
                    float* dd = d[mi][np * 2 + ns];
                    MMA_BF16(dd, ah, bh[2 * ns], bh[2 * ns + 1]);
                    MMA_BF16(dd, ah, bl[2 * ns], bl[2 * ns + 1]);
                    MMA_BF16(dd, al, bh[2 * ns], bh[2 * ns + 1]);
                }
            }
        }
    }
}

__device__ __forceinline__ void stage_w(char* smem, const float* __restrict__ Wg, int tid) {
#pragma unroll
    for (int it = 0; it < 16; it++) {
        int idx = tid + it * THREADS;
        int k = idx >> 6, np = idx & 63;
        float2 w = *(const float2*)(Wg + (size_t)k * H + 2 * np);
        uint32_t hi2, lo2; split2(w.x, w.y, hi2, lo2);
        uint32_t off = (uint32_t)k * SBW + (uint32_t)np * 4;
        *(uint32_t*)(smem + O_WHI + off) = hi2;
        *(uint32_t*)(smem + O_WLO + off) = lo2;
    }
}

__global__ void __launch_bounds__(THREADS, 1)
simple_attention_kernel(const float* __restrict__ x,
                        const float* __restrict__ W_in,
                        const float* __restrict__ b_in,
                        const float* __restrict__ W_att,
                        const float* __restrict__ b_att,
                        const float* __restrict__ gamma,
                        const float* __restrict__ beta,
                        const float* __restrict__ W_c,
                        const float* __restrict__ b_c,
                        float* __restrict__ out)
{
    extern __shared__ char smem[];
    const uint32_t sb = smem_u32(smem);
    float* part = (float*)(smem + O_PART);
    float* fin  = (float*)(smem + O_FIN);
    float* lns  = (float*)(smem + O_LN);
    float* vec  = (float*)(smem + O_VEC);

    const int tid  = threadIdx.x;
    const int wid  = tid >> 5, lane = tid & 31;
    const int base = blockIdx.x * M_ROWS;
    const int gq = wid & 3;
    const int m0 = gq * 32;
    const int n0 = (wid >> 2) * 32;
    const int wc = wid >> 2;
    const int tg = (wc << 5) + lane;

    const uint32_t aOff = (uint32_t)(m0 + (lane & 15)) * SBB + ((uint32_t)(lane >> 4) << 4);
    const uint32_t bOffT = (uint32_t)(((lane >> 3) & 1) * 8 + (lane & 7)) * SBW
                         + ((uint32_t)(n0 + ((lane >> 4) << 3)) << 1);

    const int rBase = m0 + (lane >> 2);
    const int cBase = n0 + (lane & 3) * 2;

    const float invf[KT] = {1.0f, 1.0f, 0.5f, 1.6666666667e-1f, 4.1666666667e-2f,
                            8.3333333333e-3f, 1.3888888889e-3f, 1.9841269841e-4f};

    // ---------------- initial staging ----------------
#pragma unroll
    for (int it = 0; it < 16; it++) {
        int idx = tid + it * THREADS;
        int row = idx >> 6, kp = idx & 63;
        float2 v = *(const float2*)(x + (size_t)(base + row) * H + 2 * kp);
        uint32_t hi2, lo2; split2(v.x, v.y, hi2, lo2);
        uint32_t off = (uint32_t)row * SBB + (uint32_t)kp * 4;
        *(uint32_t*)(smem + O_AHI + off) = hi2;
        *(uint32_t*)(smem + O_ALO + off) = lo2;
    }
    stage_w(smem, W_in, tid);
    if (tid < 128) vec[VF_BIAS + tid] = b_in[tid];
    for (int i = tid; i < 3 * 128; i += THREADS) {
        vec[VF_BIAS + 128 + i] = b_att[i];
        vec[VF_G + i]  = gamma[i];
        vec[VF_BE + i] = beta[i];
    }
    for (int i = tid; i < H * NC; i += THREADS) vec[VF_WC + i] = W_c[i];
    if (tid < NC) vec[VF_BC + tid] = b_c[tid];
    __syncthreads();

    float d[2][4][4];

    // ---------------- in-proj GEMM + epilogue ----------------
    mma_gemm(sb, aOff, bOffT, d);
    BARG(gq);                              // group's GEMM A-reads done before A writes
    {
        const float* sBias = vec + VF_BIAS;
#pragma unroll
        for (int mi = 0; mi < 2; mi++)
#pragma unroll
        for (int ri = 0; ri < 2; ri++) {
            int row = rBase + mi * 16 + ri * 8;
#pragma unroll
            for (int na = 0; na < 4; na++) {
                int col = cBase + na * 8;
                float v0 = d[mi][na][2 * ri]     + sBias[col];
                float v1 = d[mi][na][2 * ri + 1] + sBias[col + 1];
                uint32_t hi2, lo2; split2(v0, v1, hi2, lo2);
                uint32_t off = (uint32_t)row * SBB + (uint32_t)col * 2;
                *(uint32_t*)(smem + O_AHI + off) = hi2;
                *(uint32_t*)(smem + O_ALO + off) = lo2;
            }
        }
    }
    __syncthreads();                       // all W_in reads done
    stage_w(smem, W_att, tid);
    __syncthreads();

    // ---------------- attention layers ----------------
    for (int l = 0; l < NATT; l++) {
        const bool lastl = (l == NATT - 1);
        mma_gemm(sb, aOff, bOffT, d);
        // no barrier: pass A reads A-tiles (read-only) and writes own part slot

        const float* sBias = vec + VF_BIAS + 128 + l * 128;
        const float* sG    = vec + VF_G + l * 128;
        const float* sBe   = vec + VF_BE + l * 128;

        // ---- pass A: u = tanh(D+b); moments; quad-shfl; part ----
#pragma unroll
        for (int mi = 0; mi < 2; mi++)
#pragma unroll
        for (int ri = 0; ri < 2; ri++) {
            int row = rBase + mi * 16 + ri * 8;
            ull sm2[KT2], mm2[KT2];
#pragma unroll
            for (int p = 0; p < KT2; p++) { sm2[p] = 0ull; mm2[p] = 0ull; }
#pragma unroll
            for (int na = 0; na < 4; na++) {
                int col = cBase + na * 8;
                float u0 = fast_tanh(d[mi][na][2 * ri]     + sBias[col]);
                float u1 = fast_tanh(d[mi][na][2 * ri + 1] + sBias[col + 1]);
                d[mi][na][2 * ri]     = u0;
                d[mi][na][2 * ri + 1] = u1;
                uint32_t off = (uint32_t)row * SBB + (uint32_t)col * 2;
                float2 h = join2(*(const uint32_t*)(smem + O_AHI + off),
                                 *(const uint32_t*)(smem + O_ALO + off));
                mom_acc(sm2, mm2, u0, h.x);
                mom_acc(sm2, mm2, u1, h.y);
            }
            float v16[16];
#pragma unroll
            for (int p = 0; p < KT2; p++) {
                unpack2(sm2[p], v16[2 * p], v16[2 * p + 1]);
                unpack2(mm2[p], v16[8 + 2 * p], v16[8 + 2 * p + 1]);
            }
#pragma unroll
            for (int k = 0; k < 16; k++) {
                v16[k] += __shfl_xor_sync(0xffffffffu, v16[k], 1);
                v16[k] += __shfl_xor_sync(0xffffffffu, v16[k], 2);
            }
            int j = lane & 3;
            *(float4*)&part[row * PART_STRIDE + wc * 16 + j * 4] =
                make_float4(v16[j * 4], v16[j * 4 + 1], v16[j * 4 + 2], v16[j * 4 + 3]);
        }
        BARG(gq);

        // ---- group reduce: part -> fin ----
        {
            int row = m0 + (tg >> 2), j = tg & 3;
            float4 s = *(const float4*)&part[row * PART_STRIDE + 0 * 16 + j * 4];
#pragma unroll
            for (int q = 1; q < 4; q++) {
                float4 t = *(const float4*)&part[row * PART_STRIDE + q * 16 + j * 4];
                s.x += t.x; s.y += t.y; s.z += t.z; s.w += t.w;
            }
            *(float4*)&fin[row * FIN_STRIDE + j * 4] = s;
        }
        BARG(gq);

        // ---- pass B: Horner, z in regs, LN partials ----
#pragma unroll
        for (int mi = 0; mi < 2; mi++)
#pragma unroll
        for (int ri = 0; ri < 2; ri++) {
            int row = rBase + mi * 16 + ri * 8;
            float4 f0 = *(const float4*)&fin[row * FIN_STRIDE + 0];
            float4 f1 = *(const float4*)&fin[row * FIN_STRIDE + 4];
            float4 f2 = *(const float4*)&fin[row * FIN_STRIDE + 8];
            float4 f3 = *(const float4*)&fin[row * FIN_STRIDE + 12];
            float smv[8] = {f0.x, f0.y, f0.z, f0.w, f1.x, f1.y, f1.z, f1.w};
            float mmv[8] = {f2.x, f2.y, f2.z, f2.w, f3.x, f3.y, f3.z, f3.w};
            ull pm[KT];
#pragma unroll
            for (int k = 0; k < KT; k++) pm[k] = pack2(mmv[k] * invf[k], smv[k] * invf[k]);

            float lsum = 0.f, lsq = 0.f;
#pragma unroll
            for (int na = 0; na < 4; na++) {
                int col = cBase + na * 8;
                uint32_t off = (uint32_t)row * SBB + (uint32_t)col * 2;
                float2 h = join2(*(const uint32_t*)(smem + O_AHI + off),
                                 *(const uint32_t*)(smem + O_ALO + off));
#pragma unroll
                for (int ci = 0; ci < 2; ci++) {
                    float u = d[mi][na][2 * ri + ci];
                    ull u2 = pack2(u, u);
                    ull nd = pm[KT - 1];
#pragma unroll
                    for (int k = KT - 2; k >= 0; k--) nd = fma2(nd, u2, pm[k]);
                    float num, den; unpack2(nd, num, den);
                    float z = (ci ? h.y : h.x) + __fdividef(num, den);
                    d[mi][na][2 * ri + ci] = z;
                    lsum += z;
                    lsq = fmaf(z, z, lsq);
                }
            }
            lsum += __shfl_xor_sync(0xffffffffu, lsum, 1);
            lsum += __shfl_xor_sync(0xffffffffu, lsum, 2);
            lsq  += __shfl_xor_sync(0xffffffffu, lsq, 1);
            lsq  += __shfl_xor_sync(0xffffffffu, lsq, 2);
            if ((lane & 3) == 0)
                *(float2*)&lns[row * LN_STRIDE + wc * 2] = make_float2(lsum, lsq);
        }
        __syncthreads();   // all GEMM W-reads done + lns visible to group

        // ---- stage next W (overlaps pass C) ----
        if (!lastl) stage_w(smem, W_att + (size_t)(l + 1) * H * H, tid);

        // ---- pass C: LN apply -> A tiles, or fused classifier ----
        if (!lastl) {
#pragma unroll
            for (int mi = 0; mi < 2; mi++)
#pragma unroll
            for (int ri = 0; ri < 2; ri++) {
                int row = rBase + mi * 16 + ri * 8;
                float tsum = 0.f, tsq = 0.f;
#pragma unroll
                for (int q = 0; q < 4; q++) {
                    float2 t = *(const float2*)&lns[row * LN_STRIDE + q * 2];
                    tsum += t.x; tsq += t.y;
                }
                float mu   = tsum * (1.f / H);
                float var  = tsq * (1.f / H) - mu * mu;
                float rinv = rsqrtf(var + EPS_LN);
#pragma unroll
                for (int na = 0; na < 4; na++) {
                    int col = cBase + na * 8;
                    float hn0 = fmaf((d[mi][na][2 * ri]     - mu) * rinv, sG[col],     sBe[col]);
                    float hn1 = fmaf((d[mi][na][2 * ri + 1] - mu) * rinv, sG[col + 1], sBe[col + 1]);
                    uint32_t hi2, lo2; split2(hn0, hn1, hi2, lo2);
                    uint32_t off = (uint32_t)row * SBB + (uint32_t)col * 2;
                    *(uint32_t*)(smem + O_AHI + off) = hi2;
                    *(uint32_t*)(smem + O_ALO + off) = lo2;
                }
            }
            __syncthreads();   // W staged + A written -> next GEMM
        } else {
            const float* sWc = vec + VF_WC;
#pragma unroll
            for (int mi = 0; mi < 2; mi++)
#pragma unroll
            for (int ri = 0; ri < 2; ri++) {
                int row = rBase + mi * 16 + ri * 8;
                float tsum = 0.f, tsq = 0.f;
#pragma unroll
                for (int q = 0; q < 4; q++) {
                    float2 t = *(const float2*)&lns[row * LN_STRIDE + q * 2];
                    tsum += t.x; tsq += t.y;
                }
                float mu   = tsum * (1.f / H);
                float var  = tsq * (1.f / H) - mu * mu;
                float rinv = rsqrtf(var + EPS_LN);
                float acc[NC];
#pragma unroll
                for (int c = 0; c < NC; c++) acc[c] = 0.f;
#pragma unroll
                for (int na = 0; na < 4; na++) {
                    int col = cBase + na * 8;
                    float hn0 = fmaf((d[mi][na][2 * ri]     - mu) * rinv, sG[col],     sBe[col]);
                    float hn1 = fmaf((d[mi][na][2 * ri + 1] - mu) * rinv, sG[col + 1], sBe[col + 1]);
#pragma unroll
                    for (int c = 0; c < NC; c++)
                        acc[c] += hn0 * sWc[col * NC + c] + hn1 * sWc[(col + 1) * NC + c];
                }
#pragma unroll
                for (int c = 0; c < NC; c++) {
                    acc[c] += __shfl_xor_sync(0xffffffffu, acc[c], 1);
                    acc[c] += __shfl_xor_sync(0xffffffffu, acc[c], 2);
                }
                if ((lane & 3) == 0) {
                    float* p = &part[row * PART_STRIDE + wc * 10];
#pragma unroll
                    for (int c = 0; c < NC; c += 2)
                        *(float2*)&p[c] = make_float2(acc[c], acc[c + 1]);
                }
            }
            BARG(gq);
            if (tid < 128) {
                float o[NC];
#pragma unroll
                for (int c = 0; c < NC; c++) o[c] = vec[VF_BC + c];
#pragma unroll
                for (int q = 0; q < 4; q++)
#pragma unroll
                    for (int c = 0; c < NC; c++)
                        o[c] += part[tid * PART_STRIDE + q * 10 + c];
                float* og = out + (size_t)(base + tid) * NC;
#pragma unroll
                for (int c = 0; c < NC; c += 2)
                    *(float2*)&og[c] = make_float2(o[c], o[c + 1]);
            }
        }
    }
}

extern "C" void kernel_launch(void* const* d_in, const int* in_sizes, int n_in,
                              void* d_out, int out_size)
{
    const float* x     = (const float*)d_in[0];
    const float* W_in  = (const float*)d_in[1];
    const float* b_in  = (const float*)d_in[2];
    const float* W_att = (const float*)d_in[3];
    const float* b_att = (const float*)d_in[4];
    const float* gam   = (const float*)d_in[5];
    const float* bet   = (const float*)d_in[6];
    const float* W_c   = (const float*)d_in[7];
    const float* b_c   = (const float*)d_in[8];

    cudaFuncSetAttribute(simple_attention_kernel,
                         cudaFuncAttributeMaxDynamicSharedMemorySize, SMEM_TOTAL);

    simple_attention_kernel<<<B_TOTAL / M_ROWS, THREADS, SMEM_TOTAL>>>(
        x, W_in, b_in, W_att, b_att, gam, bet, W_c, b_c, (float*)d_out);
}

// round 13
// speedup vs baseline: 1.0375x; 1.0375x over previous
#include <cuda_runtime.h>
#include <cuda_bf16.h>
#include <math.h>
#include <stdint.h>

#define H        128
#define NC       10
#define NATT     3
#define B_TOTAL  16384
#define M_ROWS   128
#define THREADS  512
#define KT       8
#define KT2      4
#define EPS_LN   1e-5f
#define SBB      272
#define SBW      272

typedef unsigned long long ull;

// ---------------- smem byte layout ----------------
#define O_AHI  0
#define O_ALO  (O_AHI + 128 * SBB)
#define O_WHI  (O_ALO + 128 * SBB)
#define O_WLO  (O_WHI + 128 * SBW)
#define O_PART (O_WLO + 128 * SBW)
#define PART_STRIDE 68
#define O_FIN  (O_PART + 128 * PART_STRIDE * 4)
#define FIN_STRIDE 20
#define O_LN   (O_FIN + 128 * FIN_STRIDE * 4)
#define LN_STRIDE 12
#define O_VEC  (O_LN + 128 * LN_STRIDE * 4)
#define VF_BIAS 0
#define VF_G    (VF_BIAS + 4 * 128)
#define VF_BE   (VF_G + 3 * 128)
#define VF_WC   (VF_BE + 3 * 128)
#define VF_BC   (VF_WC + H * NC)
#define VF_TOT  (VF_BC + 16)
#define SMEM_TOTAL (O_VEC + VF_TOT * 4)

// ---------------- f32x2 helpers ----------------
__device__ __forceinline__ ull pack2(float lo, float hi) {
    ull r; asm("mov.b64 %0, {%1, %2};" : "=l"(r) : "f"(lo), "f"(hi)); return r;
}
__device__ __forceinline__ void unpack2(ull v, float& lo, float& hi) {
    asm("mov.b64 {%0, %1}, %2;" : "=f"(lo), "=f"(hi) : "l"(v));
}
__device__ __forceinline__ ull fma2(ull a, ull b, ull c) {
    ull d; asm("fma.rn.f32x2 %0, %1, %2, %3;" : "=l"(d) : "l"(a), "l"(b), "l"(c)); return d;
}
__device__ __forceinline__ ull add2(ull a, ull b) {
    ull d; asm("add.rn.f32x2 %0, %1, %2;" : "=l"(d) : "l"(a), "l"(b)); return d;
}
__device__ __forceinline__ ull mul2(ull a, ull b) {
    ull d; asm("mul.rn.f32x2 %0, %1, %2;" : "=l"(d) : "l"(a), "l"(b)); return d;
}

__device__ __forceinline__ uint32_t smem_u32(const void* p) {
    uint32_t a;
    asm("{ .reg .u64 t; cvta.to.shared.u64 t, %1; cvt.u32.u64 %0, t; }" : "=r"(a) : "l"(p));
    return a;
}

// ---------------- tensor-core primitives ----------------
#define LDSM4(r, addr)                                                          \
    asm volatile("ldmatrix.sync.aligned.m8n8.x4.shared.b16 {%0,%1,%2,%3}, [%4];" \
        : "=r"((r)[0]), "=r"((r)[1]), "=r"((r)[2]), "=r"((r)[3]) : "r"(addr))
#define LDSM4T(r, addr)                                                         \
    asm volatile("ldmatrix.sync.aligned.m8n8.x4.trans.shared.b16 {%0,%1,%2,%3}, [%4];" \
        : "=r"((r)[0]), "=r"((r)[1]), "=r"((r)[2]), "=r"((r)[3]) : "r"(addr))

#define MMA_BF16(d, a, b0, b1)                                                  \
    asm volatile("mma.sync.aligned.m16n8k16.row.col.f32.bf16.bf16.f32 "         \
        "{%0,%1,%2,%3}, {%4,%5,%6,%7}, {%8,%9}, {%0,%1,%2,%3};"                 \
        : "+f"((d)[0]), "+f"((d)[1]), "+f"((d)[2]), "+f"((d)[3])                \
        : "r"((a)[0]), "r"((a)[1]), "r"((a)[2]), "r"((a)[3]), "r"(b0), "r"(b1))

#define BARG(g) asm volatile("bar.sync %0, %1;" :: "r"((g) + 1), "r"(128) : "memory")

// ---------------- bf16 split/join ----------------
union BU { __nv_bfloat162 b; uint32_t u; };
__device__ __forceinline__ void split2(float v0, float v1, uint32_t& hi2, uint32_t& lo2) {
    BU h; h.b = __floats2bfloat162_rn(v0, v1);
    float r0 = v0 - __bfloat162float(__low2bfloat16(h.b));
    float r1 = v1 - __bfloat162float(__high2bfloat16(h.b));
    BU l; l.b = __floats2bfloat162_rn(r0, r1);
    hi2 = h.u; lo2 = l.u;
}
__device__ __forceinline__ float2 join2(uint32_t hi2, uint32_t lo2) {
    BU a, b; a.u = hi2; b.u = lo2;
    float2 r;
    r.x = __bfloat162float(__low2bfloat16(a.b))  + __bfloat162float(__low2bfloat16(b.b));
    r.y = __bfloat162float(__high2bfloat16(a.b)) + __bfloat162float(__high2bfloat16(b.b));
    return r;
}

// single-MUFU tanh (sm_75+): max rel err ~2^-11, well under harness gate
__device__ __forceinline__ float tanh_fast(float x) {
    float y; asm("tanh.approx.f32 %0, %1;" : "=f"(y) : "f"(x)); return y;
}

__device__ __forceinline__ void mom_acc(ull sm2[KT2], ull mm2[KT2], float u, float h) {
    float uu = u * u;
    ull pwp = pack2(1.0f, u);
    ull u2d = pack2(uu, uu);
    ull h2  = pack2(h, h);
#pragma unroll
    for (int p = 0; p < KT2; p++) {
        sm2[p] = add2(sm2[p], pwp);
        mm2[p] = fma2(pwp, h2, mm2[p]);
        if (p < KT2 - 1) pwp = mul2(pwp, u2d);
    }
}

// 3-pass bf16-split GEMM. A tile m-major (non-trans LDSM); W tile k-major (trans LDSM).
__device__ __forceinline__ void mma_gemm(uint32_t sb, uint32_t aOff, uint32_t bOffT,
                                         float d[2][4][4]) {
#pragma unroll
    for (int mi = 0; mi < 2; mi++)
#pragma unroll
        for (int na = 0; na < 4; na++)
#pragma unroll
            for (int e = 0; e < 4; e++) d[mi][na][e] = 0.f;

    const uint32_t aHi = sb + O_AHI + aOff, aLo = sb + O_ALO + aOff;
    const uint32_t bHi = sb + O_WHI + bOffT, bLo = sb + O_WLO + bOffT;
#pragma unroll
    for (int kk = 0; kk < 8; kk++) {
        uint32_t ko  = kk * 32;
        uint32_t bko = kk * 16 * SBW;
        uint32_t ahi0[4], ahi1[4], alo0[4], alo1[4];
        uint32_t bhi0[4], bhi1[4], blo0[4], blo1[4];
        LDSM4(ahi0, aHi + ko);
        LDSM4(ahi1, aHi + 16 * SBB + ko);
        LDSM4(alo0, aLo + ko);
        LDSM4(alo1, aLo + 16 * SBB + ko);
        LDSM4T(bhi0, bHi + bko);
        LDSM4T(bhi1, bHi + bko + 32);
        LDSM4T(blo0, bLo + bko);
        LDSM4T(blo1, bLo + bko + 32);
#pragma unroll
        for (int mi = 0; mi < 2; mi++) {
            uint32_t* ah = mi ? ahi1 : ahi0;
            uint32_t* al = mi ? alo1 : alo0;
#pragma unroll
            for (int np = 0; np < 2; np++) {
                uint32_t* bh = np ? bhi1 : bhi0;
                uint32_t* bl = np ? blo1 : blo0;
#pragma unroll
                for (int ns = 0; ns < 2; ns++) {
                    float* dd = d[mi][np * 2 + ns];
                    MMA_BF16(dd, ah, bh[2 * ns], bh[2 * ns + 1]);
                    MMA_BF16(dd, ah, bl[2 * ns], bl[2 * ns + 1]);
                    MMA_BF16(dd, al, bh[2 * ns], bh[2 * ns + 1]);
                }
            }
        }
    }
}

__device__ __forceinline__ void stage_w(char* smem, const float* __restrict__ Wg, int tid) {
#pragma unroll
    for (int it = 0; it < 16; it++) {
        int idx = tid + it * THREADS;
        int k = idx >> 6, np = idx & 63;
        float2 w = *(const float2*)(Wg + (size_t)k * H + 2 * np);
        uint32_t hi2, lo2; split2(w.x, w.y, hi2, lo2);
        uint32_t off = (uint32_t)k * SBW + (uint32_t)np * 4;
        *(uint32_t*)(smem + O_WHI + off) = hi2;
        *(uint32_t*)(smem + O_WLO + off) = lo2;
    }
}

__global__ void __launch_bounds__(THREADS, 1)
simple_attention_kernel(const float* __restrict__ x,
                        const float* __restrict__ W_in,
                        const float* __restrict__ b_in,
                        const float* __restrict__ W_att,
                        const float* __restrict__ b_att,
                        const float* __restrict__ gamma,
                        const float* __restrict__ beta,
                        const float* __restrict__ W_c,
                        const float* __restrict__ b_c,
                        float* __restrict__ out)
{
    extern __shared__ char smem[];
    const uint32_t sb = smem_u32(smem);
    float* part = (float*)(smem + O_PART);
    float* fin  = (float*)(smem + O_FIN);
    float* lns  = (float*)(smem + O_LN);
    float* vec  = (float*)(smem + O_VEC);

    const int tid  = threadIdx.x;
    const int wid  = tid >> 5, lane = tid & 31;
    const int base = blockIdx.x * M_ROWS;
    const int gq = wid & 3;
    const int m0 = gq * 32;
    const int n0 = (wid >> 2) * 32;
    const int wc = wid >> 2;
    const int tg = (wc << 5) + lane;

    const uint32_t aOff = (uint32_t)(m0 + (lane & 15)) * SBB + ((uint32_t)(lane >> 4) << 4);
    const uint32_t bOffT = (uint32_t)(((lane >> 3) & 1) * 8 + (lane & 7)) * SBW
                         + ((uint32_t)(n0 + ((lane >> 4) << 3)) << 1);

    const int rBase = m0 + (lane >> 2);
    const int cBase = n0 + (lane & 3) * 2;

    const float invf[KT] = {1.0f, 1.0f, 0.5f, 1.6666666667e-1f, 4.1666666667e-2f,
                            8.3333333333e-3f, 1.3888888889e-3f, 1.9841269841e-4f};

    // ---------------- initial staging ----------------
#pragma unroll
    for (int it = 0; it < 16; it++) {
        int idx = tid + it * THREADS;
        int row = idx >> 6, kp = idx & 63;
        float2 v = *(const float2*)(x + (size_t)(base + row) * H + 2 * kp);
        uint32_t hi2, lo2; split2(v.x, v.y, hi2, lo2);
        uint32_t off = (uint32_t)row * SBB + (uint32_t)kp * 4;
        *(uint32_t*)(smem + O_AHI + off) = hi2;
        *(uint32_t*)(smem + O_ALO + off) = lo2;
    }
    stage_w(smem, W_in, tid);
    if (tid < 128) vec[VF_BIAS + tid] = b_in[tid];
    for (int i = tid; i < 3 * 128; i += THREADS) {
        vec[VF_BIAS + 128 + i] = b_att[i];
        vec[VF_G + i]  = gamma[i];
        vec[VF_BE + i] = beta[i];
    }
    for (int i = tid; i < H * NC; i += THREADS) vec[VF_WC + i] = W_c[i];
    if (tid < NC) vec[VF_BC + tid] = b_c[tid];
    __syncthreads();

    float d[2][4][4];

    // ---------------- in-proj GEMM + epilogue ----------------
    mma_gemm(sb, aOff, bOffT, d);
    BARG(gq);
    {
        const float* sBias = vec + VF_BIAS;
#pragma unroll
        for (int mi = 0; mi < 2; mi++)
#pragma unroll
        for (int ri = 0; ri < 2; ri++) {
            int row = rBase + mi * 16 + ri * 8;
#pragma unroll
            for (int na = 0; na < 4; na++) {
                int col = cBase + na * 8;
                float v0 = d[mi][na][2 * ri]     + sBias[col];
                float v1 = d[mi][na][2 * ri + 1] + sBias[col + 1];
                uint32_t hi2, lo2; split2(v0, v1, hi2, lo2);
                uint32_t off = (uint32_t)row * SBB + (uint32_t)col * 2;
                *(uint32_t*)(smem + O_AHI + off) = hi2;
                *(uint32_t*)(smem + O_ALO + off) = lo2;
            }
        }
    }
    __syncthreads();
    stage_w(smem, W_att, tid);
    __syncthreads();

    // ---------------- attention layers ----------------
    for (int l = 0; l < NATT; l++) {
        const bool lastl = (l == NATT - 1);
        mma_gemm(sb, aOff, bOffT, d);

        const float* sBias = vec + VF_BIAS + 128 + l * 128;
        const float* sG    = vec + VF_G + l * 128;
        const float* sBe   = vec + VF_BE + l * 128;

        // h cached in regs for pass A -> pass B (loaded once per layer)
        float hreg[2][4][4];

        // ---- pass A: u = tanh(D+b); moments; quad-shfl; part ----
#pragma unroll
        for (int mi = 0; mi < 2; mi++)
#pragma unroll
        for (int ri = 0; ri < 2; ri++) {
            int row = rBase + mi * 16 + ri * 8;
            ull sm2[KT2], mm2[KT2];
#pragma unroll
            for (int p = 0; p < KT2; p++) { sm2[p] = 0ull; mm2[p] = 0ull; }
#pragma unroll
            for (int na = 0; na < 4; na++) {
                int col = cBase + na * 8;
                float u0 = tanh_fast(d[mi][na][2 * ri]     + sBias[col]);
                float u1 = tanh_fast(d[mi][na][2 * ri + 1] + sBias[col + 1]);
                d[mi][na][2 * ri]     = u0;
                d[mi][na][2 * ri + 1] = u1;
                uint32_t off = (uint32_t)row * SBB + (uint32_t)col * 2;
                float2 h = join2(*(const uint32_t*)(smem + O_AHI + off),
                                 *(const uint32_t*)(smem + O_ALO + off));
                hreg[mi][na][2 * ri]     = h.x;
                hreg[mi][na][2 * ri + 1] = h.y;
                mom_acc(sm2, mm2, u0, h.x);
                mom_acc(sm2, mm2, u1, h.y);
            }
            float v16[16];
#pragma unroll
            for (int p = 0; p < KT2; p++) {
                unpack2(sm2[p], v16[2 * p], v16[2 * p + 1]);
                unpack2(mm2[p], v16[8 + 2 * p], v16[8 + 2 * p + 1]);
            }
#pragma unroll
            for (int k = 0; k < 16; k++) {
                v16[k] += __shfl_xor_sync(0xffffffffu, v16[k], 1);
                v16[k] += __shfl_xor_sync(0xffffffffu, v16[k], 2);
            }
            int j = lane & 3;
            *(float4*)&part[row * PART_STRIDE + wc * 16 + j * 4] =
                make_float4(v16[j * 4], v16[j * 4 + 1], v16[j * 4 + 2], v16[j * 4 + 3]);
        }
        BARG(gq);

        // ---- group reduce: part -> fin ----
        {
            int row = m0 + (tg >> 2), j = tg & 3;
            float4 s = *(const float4*)&part[row * PART_STRIDE + 0 * 16 + j * 4];
#pragma unroll
            for (int q = 1; q < 4; q++) {
                float4 t = *(const float4*)&part[row * PART_STRIDE + q * 16 + j * 4];
                s.x += t.x; s.y += t.y; s.z += t.z; s.w += t.w;
            }
            *(float4*)&fin[row * FIN_STRIDE + j * 4] = s;
        }
        BARG(gq);

        // ---- pass B: Horner, z in regs, LN partials ----
#pragma unroll
        for (int mi = 0; mi < 2; mi++)
#pragma unroll
        for (int ri = 0; ri < 2; ri++) {
            int row = rBase + mi * 16 + ri * 8;
            float4 f0 = *(const float4*)&fin[row * FIN_STRIDE + 0];
            float4 f1 = *(const float4*)&fin[row * FIN_STRIDE + 4];
            float4 f2 = *(const float4*)&fin[row * FIN_STRIDE + 8];
            float4 f3 = *(const float4*)&fin[row * FIN_STRIDE + 12];
            float smv[8] = {f0.x, f0.y, f0.z, f0.w, f1.x, f1.y, f1.z, f1.w};
            float mmv[8] = {f2.x, f2.y, f2.z, f2.w, f3.x, f3.y, f3.z, f3.w};
            ull pm[KT];
#pragma unroll
            for (int k = 0; k < KT; k++) pm[k] = pack2(mmv[k] * invf[k], smv[k] * invf[k]);

            float lsum = 0.f, lsq = 0.f;
#pragma unroll
            for (int na = 0; na < 4; na++) {
#pragma unroll
                for (int ci = 0; ci < 2; ci++) {
                    float u = d[mi][na][2 * ri + ci];
                    ull u2 = pack2(u, u);
                    ull nd = pm[KT - 1];
#pragma unroll
                    for (int k = KT - 2; k >= 0; k--) nd = fma2(nd, u2, pm[k]);
                    float num, den; unpack2(nd, num, den);
                    float z = hreg[mi][na][2 * ri + ci] + __fdividef(num, den);
                    d[mi][na][2 * ri + ci] = z;
                    lsum += z;
                    lsq = fmaf(z, z, lsq);
                }
            }
            lsum += __shfl_xor_sync(0xffffffffu, lsum, 1);
            lsum += __shfl_xor_sync(0xffffffffu, lsum, 2);
            lsq  += __shfl_xor_sync(0xffffffffu, lsq, 1);
            lsq  += __shfl_xor_sync(0xffffffffu, lsq, 2);
            if ((lane & 3) == 0)
                *(float2*)&lns[row * LN_STRIDE + wc * 2] = make_float2(lsum, lsq);
        }
        __syncthreads();   // all GEMM W-reads done + lns visible

        // ---- stage next W (overlaps pass C) ----
        if (!lastl) stage_w(smem, W_att + (size_t)(l + 1) * H * H, tid);

        // ---- pass C: LN apply -> A tiles, or fused classifier ----
        if (!lastl) {
#pragma unroll
            for (int mi = 0; mi < 2; mi++)
#pragma unroll
            for (int ri = 0; ri < 2; ri++) {
                int row = rBase + mi * 16 + ri * 8;
                float tsum = 0.f, tsq = 0.f;
#pragma unroll
                for (int q = 0; q < 4; q++) {
                    float2 t = *(const float2*)&lns[row * LN_STRIDE + q * 2];
                    tsum += t.x; tsq += t.y;
                }
                float mu   = tsum * (1.f / H);
                float var  = tsq * (1.f / H) - mu * mu;
                float rinv = rsqrtf(var + EPS_LN);
#pragma unroll
                for (int na = 0; na < 4; na++) {
                    int col = cBase + na * 8;
                    float hn0 = fmaf((d[mi][na][2 * ri]     - mu) * rinv, sG[col],     sBe[col]);
                    float hn1 = fmaf((d[mi][na][2 * ri + 1] - mu) * rinv, sG[col + 1], sBe[col + 1]);
                    uint32_t hi2, lo2; split2(hn0, hn1, hi2, lo2);
                    uint32_t off = (uint32_t)row * SBB + (uint32_t)col * 2;
                    *(uint32_t*)(smem + O_AHI + off) = hi2;
                    *(uint32_t*)(smem + O_ALO + off) = lo2;
                }
            }
            __syncthreads();
        } else {
            const float* sWc = vec + VF_WC;
#pragma unroll
            for (int mi = 0; mi < 2; mi++)
#pragma unroll
            for (int ri = 0; ri < 2; ri++) {
                int row = rBase + mi * 16 + ri * 8;
                float tsum = 0.f, tsq = 0.f;
#pragma unroll
                for (int q = 0; q < 4; q++) {
                    float2 t = *(const float2*)&lns[row * LN_STRIDE + q * 2];
                    tsum += t.x; tsq += t.y;
                }
                float mu   = tsum * (1.f / H);
                float var  = tsq * (1.f / H) - mu * mu;
                float rinv = rsqrtf(var + EPS_LN);
                float acc[NC];
#pragma unroll
                for (int c = 0; c < NC; c++) acc[c] = 0.f;
#pragma unroll
                for (int na = 0; na < 4; na++) {
                    int col = cBase + na * 8;
                    float hn0 = fmaf((d[mi][na][2 * ri]     - mu) * rinv, sG[col],     sBe[col]);
                    float hn1 = fmaf((d[mi][na][2 * ri + 1] - mu) * rinv, sG[col + 1], sBe[col + 1]);
#pragma unroll
                    for (int c = 0; c < NC; c++)
                        acc[c] += hn0 * sWc[col * NC + c] + hn1 * sWc[(col + 1) * NC + c];
                }
#pragma unroll
                for (int c = 0; c < NC; c++) {
                    acc[c] += __shfl_xor_sync(0xffffffffu, acc[c], 1);
                    acc[c] += __shfl_xor_sync(0xffffffffu, acc[c], 2);
                }
                if ((lane & 3) == 0) {
                    float* p = &part[row * PART_STRIDE + wc * 10];
#pragma unroll
                    for (int c = 0; c < NC; c += 2)
                        *(float2*)&p[c] = make_float2(acc[c], acc[c + 1]);
                }
            }
            BARG(gq);
            if (tid < 128) {
                float o[NC];
#pragma unroll
                for (int c = 0; c < NC; c++) o[c] = vec[VF_BC + c];
#pragma unroll
                for (int q = 0; q < 4; q++)
#pragma unroll
                    for (int c = 0; c < NC; c++)
                        o[c] += part[tid * PART_STRIDE + q * 10 + c];
                float* og = out + (size_t)(base + tid) * NC;
#pragma unroll
                for (int c = 0; c < NC; c += 2)
                    *(float2*)&og[c] = make_float2(o[c], o[c + 1]);
            }
        }
    }
}

extern "C" void kernel_launch(void* const* d_in, const int* in_sizes, int n_in,
                              void* d_out, int out_size)
{
    const float* x     = (const float*)d_in[0];
    const float* W_in  = (const float*)d_in[1];
    const float* b_in  = (const float*)d_in[2];
    const float* W_att = (const float*)d_in[3];
    const float* b_att = (const float*)d_in[4];
    const float* gam   = (const float*)d_in[5];
    const float* bet   = (const float*)d_in[6];
    const float* W_c   = (const float*)d_in[7];
    const float* b_c   = (const float*)d_in[8];

    cudaFuncSetAttribute(simple_attention_kernel,
                         cudaFuncAttributeMaxDynamicSharedMemorySize, SMEM_TOTAL);

    simple_attention_kernel<<<B_TOTAL / M_ROWS, THREADS, SMEM_TOTAL>>>(
        x, W_in, b_in, W_att, b_att, gam, bet, W_c, b_c, (float*)d_out);
}

// round 15
// speedup vs baseline: 1.0423x; 1.0047x over previous
#include <cuda_runtime.h>
#include <cuda_bf16.h>
#include <math.h>
#include <stdint.h>

#define H        128
#define NC       10
#define NATT     3
#define B_TOTAL  16384
#define M_ROWS   128
#define THREADS  512
#define KT       8
#define KT2      4
#define EPS_LN   1e-5f
#define SBB      272
#define SBW      272

typedef unsigned long long ull;

// ---------------- smem byte layout ----------------
#define O_AHI  0
#define O_ALO  (O_AHI + 128 * SBB)
#define O_WHI  (O_ALO + 128 * SBB)
#define O_WLO  (O_WHI + 128 * SBW)
#define O_PART (O_WLO + 128 * SBW)
#define PART_STRIDE 68
#define O_FIN  (O_PART + 128 * PART_STRIDE * 4)
#define FIN_STRIDE 20
#define O_LN   (O_FIN + 128 * FIN_STRIDE * 4)
#define LN_STRIDE 12
#define O_VEC  (O_LN + 128 * LN_STRIDE * 4)
#define VF_BIAS 0
#define VF_G    (VF_BIAS + 4 * 128)
#define VF_BE   (VF_G + 3 * 128)
#define VF_WC   (VF_BE + 3 * 128)
#define VF_BC   (VF_WC + H * NC)
#define VF_TOT  (VF_BC + 16)
#define SMEM_TOTAL (O_VEC + VF_TOT * 4)

// ---------------- f32x2 helpers ----------------
__device__ __forceinline__ ull pack2(float lo, float hi) {
    ull r; asm("mov.b64 %0, {%1, %2};" : "=l"(r) : "f"(lo), "f"(hi)); return r;
}
__device__ __forceinline__ void unpack2(ull v, float& lo, float& hi) {
    asm("mov.b64 {%0, %1}, %2;" : "=f"(lo), "=f"(hi) : "l"(v));
}
__device__ __forceinline__ ull fma2(ull a, ull b, ull c) {
    ull d; asm("fma.rn.f32x2 %0, %1, %2, %3;" : "=l"(d) : "l"(a), "l"(b), "l"(c)); return d;
}
__device__ __forceinline__ ull add2(ull a, ull b) {
    ull d; asm("add.rn.f32x2 %0, %1, %2;" : "=l"(d) : "l"(a), "l"(b)); return d;
}
__device__ __forceinline__ ull mul2(ull a, ull b) {
    ull d; asm("mul.rn.f32x2 %0, %1, %2;" : "=l"(d) : "l"(a), "l"(b)); return d;
}

__device__ __forceinline__ uint32_t smem_u32(const void* p) {
    uint32_t a;
    asm("{ .reg .u64 t; cvta.to.shared.u64 t, %1; cvt.u32.u64 %0, t; }" : "=r"(a) : "l"(p));
    return a;
}

// ---------------- tensor-core primitives ----------------
#define LDSM4(r, addr)                                                          \
    asm volatile("ldmatrix.sync.aligned.m8n8.x4.shared.b16 {%0,%1,%2,%3}, [%4];" \
        : "=r"((r)[0]), "=r"((r)[1]), "=r"((r)[2]), "=r"((r)[3]) : "r"(addr))
#define LDSM4T(r, addr)                                                         \
    asm volatile("ldmatrix.sync.aligned.m8n8.x4.trans.shared.b16 {%0,%1,%2,%3}, [%4];" \
        : "=r"((r)[0]), "=r"((r)[1]), "=r"((r)[2]), "=r"((r)[3]) : "r"(addr))

#define MMA_BF16(d, a, b0, b1)                                                  \
    asm volatile("mma.sync.aligned.m16n8k16.row.col.f32.bf16.bf16.f32 "         \
        "{%0,%1,%2,%3}, {%4,%5,%6,%7}, {%8,%9}, {%0,%1,%2,%3};"                 \
        : "+f"((d)[0]), "+f"((d)[1]), "+f"((d)[2]), "+f"((d)[3])                \
        : "r"((a)[0]), "r"((a)[1]), "r"((a)[2]), "r"((a)[3]), "r"(b0), "r"(b1))

#define BARG(g) asm volatile("bar.sync %0, %1;" :: "r"((g) + 1), "r"(128) : "memory")

// ---------------- bf16 split ----------------
union BU { __nv_bfloat162 b; uint32_t u; };
__device__ __forceinline__ void split2(float v0, float v1, uint32_t& hi2, uint32_t& lo2) {
    BU h; h.b = __floats2bfloat162_rn(v0, v1);
    float r0 = v0 - __bfloat162float(__low2bfloat16(h.b));
    float r1 = v1 - __bfloat162float(__high2bfloat16(h.b));
    BU l; l.b = __floats2bfloat162_rn(r0, r1);
    hi2 = h.u; lo2 = l.u;
}

__device__ __forceinline__ float tanh_fast(float x) {
    float y; asm("tanh.approx.f32 %0, %1;" : "=f"(y) : "f"(x)); return y;
}

__device__ __forceinline__ void mom_acc(ull sm2[KT2], ull mm2[KT2], float u, float h) {
    float uu = u * u;
    ull pwp = pack2(1.0f, u);
    ull u2d = pack2(uu, uu);
    ull h2  = pack2(h, h);
#pragma unroll
    for (int p = 0; p < KT2; p++) {
        sm2[p] = add2(sm2[p], pwp);
        mm2[p] = fma2(pwp, h2, mm2[p]);
        if (p < KT2 - 1) pwp = mul2(pwp, u2d);
    }
}

// 3-pass bf16-split GEMM. A tile m-major (non-trans LDSM); W tile k-major (trans LDSM).
__device__ __forceinline__ void mma_gemm(uint32_t sb, uint32_t aOff, uint32_t bOffT,
                                         float d[2][4][4]) {
#pragma unroll
    for (int mi = 0; mi < 2; mi++)
#pragma unroll
        for (int na = 0; na < 4; na++)
#pragma unroll
            for (int e = 0; e < 4; e++) d[mi][na][e] = 0.f;

    const uint32_t aHi = sb + O_AHI + aOff, aLo = sb + O_ALO + aOff;
    const uint32_t bHi = sb + O_WHI + bOffT, bLo = sb + O_WLO + bOffT;
#pragma unroll
    for (int kk = 0; kk < 8; kk++) {
        uint32_t ko  = kk * 32;
        uint32_t bko = kk * 16 * SBW;
        uint32_t ahi0[4], ahi1[4], alo0[4], alo1[4];
        uint32_t bhi0[4], bhi1[4], blo0[4], blo1[4];
        LDSM4(ahi0, aHi + ko);
        LDSM4(ahi1, aHi + 16 * SBB + ko);
        LDSM4(alo0, aLo + ko);
        LDSM4(alo1, aLo + 16 * SBB + ko);
        LDSM4T(bhi0, bHi + bko);
        LDSM4T(bhi1, bHi + bko + 32);
        LDSM4T(blo0, bLo + bko);
        LDSM4T(blo1, bLo + bko + 32);
#pragma unroll
        for (int mi = 0; mi < 2; mi++) {
            uint32_t* ah = mi ? ahi1 : ahi0;
            uint32_t* al = mi ? alo1 : alo0;
#pragma unroll
            for (int np = 0; np < 2; np++) {
                uint32_t* bh = np ? bhi1 : bhi0;
                uint32_t* bl = np ? blo1 : blo0;
#pragma unroll
                for (int ns = 0; ns < 2; ns++) {
                    float* dd = d[mi][np * 2 + ns];
                    MMA_BF16(dd, ah, bh[2 * ns], bh[2 * ns + 1]);
                    MMA_BF16(dd, ah, bl[2 * ns], bl[2 * ns + 1]);
                    MMA_BF16(dd, al, bh[2 * ns], bh[2 * ns + 1]);
                }
            }
        }
    }
}

__device__ __forceinline__ void stage_w(char* smem, const float* __restrict__ Wg, int tid) {
#pragma unroll
    for (int it = 0; it < 16; it++) {
        int idx = tid + it * THREADS;
        int k = idx >> 6, np = idx & 63;
        float2 w = *(const float2*)(Wg + (size_t)k * H + 2 * np);
        uint32_t hi2, lo2; split2(w.x, w.y, hi2, lo2);
        uint32_t off = (uint32_t)k * SBW + (uint32_t)np * 4;
        *(uint32_t*)(smem + O_WHI + off) = hi2;
        *(uint32_t*)(smem + O_WLO + off) = lo2;
    }
}

__global__ void __launch_bounds__(THREADS, 1)
simple_attention_kernel(const float* __restrict__ x,
                        const float* __restrict__ W_in,
                        const float* __restrict__ b_in,
                        const float* __restrict__ W_att,
                        const float* __restrict__ b_att,
                        const float* __restrict__ gamma,
                        const float* __restrict__ beta,
                        const float* __restrict__ W_c,
                        const float* __restrict__ b_c,
                        float* __restrict__ out)
{
    extern __shared__ char smem[];
    const uint32_t sb = smem_u32(smem);
    float* part = (float*)(smem + O_PART);
    float* fin  = (float*)(smem + O_FIN);
    float* lns  = (float*)(smem + O_LN);
    float* vec  = (float*)(smem + O_VEC);

    const int tid  = threadIdx.x;
    const int wid  = tid >> 5, lane = tid & 31;
    const int base = blockIdx.x * M_ROWS;
    const int gq = wid & 3;
    const int m0 = gq * 32;
    const int n0 = (wid >> 2) * 32;
    const int wc = wid >> 2;
    const int tg = (wc << 5) + lane;

    const uint32_t aOff = (uint32_t)(m0 + (lane & 15)) * SBB + ((uint32_t)(lane >> 4) << 4);
    const uint32_t bOffT = (uint32_t)(((lane >> 3) & 1) * 8 + (lane & 7)) * SBW
                         + ((uint32_t)(n0 + ((lane >> 4) << 3)) << 1);

    const int rBase = m0 + (lane >> 2);
    const int cBase = n0 + (lane & 3) * 2;

    const float invf[KT] = {1.0f, 1.0f, 0.5f, 1.6666666667e-1f, 4.1666666667e-2f,
                            8.3333333333e-3f, 1.3888888889e-3f, 1.9841269841e-4f};

    // ---------------- initial staging ----------------
#pragma unroll
    for (int it = 0; it < 16; it++) {
        int idx = tid + it * THREADS;
        int row = idx >> 6, kp = idx & 63;
        float2 v = *(const float2*)(x + (size_t)(base + row) * H + 2 * kp);
        uint32_t hi2, lo2; split2(v.x, v.y, hi2, lo2);
        uint32_t off = (uint32_t)row * SBB + (uint32_t)kp * 4;
        *(uint32_t*)(smem + O_AHI + off) = hi2;
        *(uint32_t*)(smem + O_ALO + off) = lo2;
    }
    stage_w(smem, W_in, tid);
    if (tid < 128) vec[VF_BIAS + tid] = b_in[tid];
    for (int i = tid; i < 3 * 128; i += THREADS) {
        vec[VF_BIAS + 128 + i] = b_att[i];
        vec[VF_G + i]  = gamma[i];
        vec[VF_BE + i] = beta[i];
    }
    for (int i = tid; i < H * NC; i += THREADS) vec[VF_WC + i] = W_c[i];
    if (tid < NC) vec[VF_BC + tid] = b_c[tid];
    __syncthreads();

    float d[2][4][4];
    float hreg[2][4][4];   // persistent h for this thread's owned (row, col) elements

    // ---------------- in-proj GEMM + epilogue (seeds hreg) ----------------
    mma_gemm(sb, aOff, bOffT, d);
    BARG(gq);
    {
        const float* sBias = vec + VF_BIAS;
#pragma unroll
        for (int mi = 0; mi < 2; mi++)
#pragma unroll
        for (int ri = 0; ri < 2; ri++) {
            int row = rBase + mi * 16 + ri * 8;
#pragma unroll
            for (int na = 0; na < 4; na++) {
                int col = cBase + na * 8;
                float v0 = d[mi][na][2 * ri]     + sBias[col];
                float v1 = d[mi][na][2 * ri + 1] + sBias[col + 1];
                hreg[mi][na][2 * ri]     = v0;
                hreg[mi][na][2 * ri + 1] = v1;
                uint32_t hi2, lo2; split2(v0, v1, hi2, lo2);
                uint32_t off = (uint32_t)row * SBB + (uint32_t)col * 2;
                *(uint32_t*)(smem + O_AHI + off) = hi2;
                *(uint32_t*)(smem + O_ALO + off) = lo2;
            }
        }
    }
    __syncthreads();
    stage_w(smem, W_att, tid);
    __syncthreads();

    // ---------------- attention layers ----------------
    for (int l = 0; l < NATT; l++) {
        const bool lastl = (l == NATT - 1);
        mma_gemm(sb, aOff, bOffT, d);

        const float* sBias = vec + VF_BIAS + 128 + l * 128;
        const float* sG    = vec + VF_G + l * 128;
        const float* sBe   = vec + VF_BE + l * 128;

        // ---- pass A: u = tanh(D+b); moments from hreg; quad-shfl; part ----
#pragma unroll
        for (int mi = 0; mi < 2; mi++)
#pragma unroll
        for (int ri = 0; ri < 2; ri++) {
            int row = rBase + mi * 16 + ri * 8;
            ull sm2[KT2], mm2[KT2];
#pragma unroll
            for (int p = 0; p < KT2; p++) { sm2[p] = 0ull; mm2[p] = 0ull; }
#pragma unroll
            for (int na = 0; na < 4; na++) {
                int col = cBase + na * 8;
                float u0 = tanh_fast(d[mi][na][2 * ri]     + sBias[col]);
                float u1 = tanh_fast(d[mi][na][2 * ri + 1] + sBias[col + 1]);
                d[mi][na][2 * ri]     = u0;
                d[mi][na][2 * ri + 1] = u1;
                mom_acc(sm2, mm2, u0, hreg[mi][na][2 * ri]);
                mom_acc(sm2, mm2, u1, hreg[mi][na][2 * ri + 1]);
            }
            float v16[16];
#pragma unroll
            for (int p = 0; p < KT2; p++) {
                unpack2(sm2[p], v16[2 * p], v16[2 * p + 1]);
                unpack2(mm2[p], v16[8 + 2 * p], v16[8 + 2 * p + 1]);
            }
#pragma unroll
            for (int k = 0; k < 16; k++) {
                v16[k] += __shfl_xor_sync(0xffffffffu, v16[k], 1);
                v16[k] += __shfl_xor_sync(0xffffffffu, v16[k], 2);
            }
            int j = lane & 3;
            *(float4*)&part[row * PART_STRIDE + wc * 16 + j * 4] =
                make_float4(v16[j * 4], v16[j * 4 + 1], v16[j * 4 + 2], v16[j * 4 + 3]);
        }
        BARG(gq);

        // ---- group reduce: part -> fin ----
        {
            int row = m0 + (tg >> 2), j = tg & 3;
            float4 s = *(const float4*)&part[row * PART_STRIDE + 0 * 16 + j * 4];
#pragma unroll
            for (int q = 1; q < 4; q++) {
                float4 t = *(const float4*)&part[row * PART_STRIDE + q * 16 + j * 4];
                s.x += t.x; s.y += t.y; s.z += t.z; s.w += t.w;
            }
            *(float4*)&fin[row * FIN_STRIDE + j * 4] = s;
        }
        BARG(gq);

        // ---- pass B: Horner, z into hreg-slot path, LN partials ----
#pragma unroll
        for (int mi = 0; mi < 2; mi++)
#pragma unroll
        for (int ri = 0; ri < 2; ri++) {
            int row = rBase + mi * 16 + ri * 8;
            float4 f0 = *(const float4*)&fin[row * FIN_STRIDE + 0];
            float4 f1 = *(const float4*)&fin[row * FIN_STRIDE + 4];
            float4 f2 = *(const float4*)&fin[row * FIN_STRIDE + 8];
            float4 f3 = *(const float4*)&fin[row * FIN_STRIDE + 12];
            float smv[8] = {f0.x, f0.y, f0.z, f0.w, f1.x, f1.y, f1.z, f1.w};
            float mmv[8] = {f2.x, f2.y, f2.z, f2.w, f3.x, f3.y, f3.z, f3.w};
            ull pm[KT];
#pragma unroll
            for (int k = 0; k < KT; k++) pm[k] = pack2(mmv[k] * invf[k], smv[k] * invf[k]);

            float lsum = 0.f, lsq = 0.f;
#pragma unroll
            for (int na = 0; na < 4; na++) {
#pragma unroll
                for (int ci = 0; ci < 2; ci++) {
                    float u = d[mi][na][2 * ri + ci];
                    ull u2 = pack2(u, u);
                    ull nd = pm[KT - 1];
#pragma unroll
                    for (int k = KT - 2; k >= 0; k--) nd = fma2(nd, u2, pm[k]);
                    float num, den; unpack2(nd, num, den);
                    float z = hreg[mi][na][2 * ri + ci] + __fdividef(num, den);
                    d[mi][na][2 * ri + ci] = z;
                    lsum += z;
                    lsq = fmaf(z, z, lsq);
                }
            }
            lsum += __shfl_xor_sync(0xffffffffu, lsum, 1);
            lsum += __shfl_xor_sync(0xffffffffu, lsum, 2);
            lsq  += __shfl_xor_sync(0xffffffffu, lsq, 1);
            lsq  += __shfl_xor_sync(0xffffffffu, lsq, 2);
            if ((lane & 3) == 0)
                *(float2*)&lns[row * LN_STRIDE + wc * 2] = make_float2(lsum, lsq);
        }
        __syncthreads();   // all GEMM W-reads done + lns visible

        // ---- stage next W (overlaps pass C) ----
        if (!lastl) stage_w(smem, W_att + (size_t)(l + 1) * H * H, tid);

        // ---- pass C: LN apply -> hreg + A tiles, or fused classifier ----
        if (!lastl) {
#pragma unroll
            for (int mi = 0; mi < 2; mi++)
#pragma unroll
            for (int ri = 0; ri < 2; ri++) {
                int row = rBase + mi * 16 + ri * 8;
                float tsum = 0.f, tsq = 0.f;
#pragma unroll
                for (int q = 0; q < 4; q++) {
                    float2 t = *(const float2*)&lns[row * LN_STRIDE + q * 2];
                    tsum += t.x; tsq += t.y;
                }
                float mu   = tsum * (1.f / H);
                float var  = tsq * (1.f / H) - mu * mu;
                float rinv = rsqrtf(var + EPS_LN);
#pragma unroll
                for (int na = 0; na < 4; na++) {
                    int col = cBase + na * 8;
                    float hn0 = fmaf((d[mi][na][2 * ri]     - mu) * rinv, sG[col],     sBe[col]);
                    float hn1 = fmaf((d[mi][na][2 * ri + 1] - mu) * rinv, sG[col + 1], sBe[col + 1]);
                    hreg[mi][na][2 * ri]     = hn0;
                    hreg[mi][na][2 * ri + 1] = hn1;
                    uint32_t hi2, lo2; split2(hn0, hn1, hi2, lo2);
                    uint32_t off = (uint32_t)row * SBB + (uint32_t)col * 2;
                    *(uint32_t*)(smem + O_AHI + off) = hi2;
                    *(uint32_t*)(smem + O_ALO + off) = lo2;
                }
            }
            __syncthreads();
        } else {
            const float* sWc = vec + VF_WC;
#pragma unroll
            for (int mi = 0; mi < 2; mi++)
#pragma unroll
            for (int ri = 0; ri < 2; ri++) {
                int row = rBase + mi * 16 + ri * 8;
                float tsum = 0.f, tsq = 0.f;
#pragma unroll
                for (int q = 0; q < 4; q++) {
                    float2 t = *(const float2*)&lns[row * LN_STRIDE + q * 2];
                    tsum += t.x; tsq += t.y;
                }
                float mu   = tsum * (1.f / H);
                float var  = tsq * (1.f / H) - mu * mu;
                float rinv = rsqrtf(var + EPS_LN);
                float acc[NC];
#pragma unroll
                for (int c = 0; c < NC; c++) acc[c] = 0.f;
#pragma unroll
                for (int na = 0; na < 4; na++) {
                    int col = cBase + na * 8;
                    float hn0 = fmaf((d[mi][na][2 * ri]     - mu) * rinv, sG[col],     sBe[col]);
                    float hn1 = fmaf((d[mi][na][2 * ri + 1] - mu) * rinv, sG[col + 1], sBe[col + 1]);
#pragma unroll
                    for (int c = 0; c < NC; c++)
                        acc[c] += hn0 * sWc[col * NC + c] + hn1 * sWc[(col + 1) * NC + c];
                }
#pragma unroll
                for (int c = 0; c < NC; c++) {
                    acc[c] += __shfl_xor_sync(0xffffffffu, acc[c], 1);
                    acc[c] += __shfl_xor_sync(0xffffffffu, acc[c], 2);
                }
                if ((lane & 3) == 0) {
                    float* p = &part[row * PART_STRIDE + wc * 10];
#pragma unroll
                    for (int c = 0; c < NC; c += 2)
                        *(float2*)&p[c] = make_float2(acc[c], acc[c + 1]);
                }
            }
            BARG(gq);
            if (tid < 128) {
                float o[NC];
#pragma unroll
                for (int c = 0; c < NC; c++) o[c] = vec[VF_BC + c];
#pragma unroll
                for (int q = 0; q < 4; q++)
#pragma unroll
                    for (int c = 0; c < NC; c++)
                        o[c] += part[tid * PART_STRIDE + q * 10 + c];
                float* og = out + (size_t)(base + tid) * NC;
#pragma unroll
                for (int c = 0; c < NC; c += 2)
                    *(float2*)&og[c] = make_float2(o[c], o[c + 1]);
            }
        }
    }
}

extern "C" void kernel_launch(void* const* d_in, const int* in_sizes, int n_in,
                              void* d_out, int out_size)
{
    const float* x     = (const float*)d_in[0];
    const float* W_in  = (const float*)d_in[1];
    const float* b_in  = (const float*)d_in[2];
    const float* W_att = (const float*)d_in[3];
    const float* b_att = (const float*)d_in[4];
    const float* gam   = (const float*)d_in[5];
    const float* bet   = (const float*)d_in[6];
    const float* W_c   = (const float*)d_in[7];
    const float* b_c   = (const float*)d_in[8];

    cudaFuncSetAttribute(simple_attention_kernel,
                         cudaFuncAttributeMaxDynamicSharedMemorySize, SMEM_TOTAL);

    simple_attention_kernel<<<B_TOTAL / M_ROWS, THREADS, SMEM_TOTAL>>>(
        x, W_in, b_in, W_att, b_att, gam, bet, W_c, b_c, (float*)d_out);
}

// round 16
// speedup vs baseline: 1.0430x; 1.0007x over previous
#include <cuda_runtime.h>
#include <cuda_bf16.h>
#include <math.h>
#include <stdint.h>

#define H        128
#define NC       10
#define NATT     3
#define B_TOTAL  16384
#define M_ROWS   64
#define THREADS  256
#define KT       8
#define KT2      4
#define EPS_LN   1e-5f
#define SBB      272
#define SBW      272

typedef unsigned long long ull;

// ---------------- smem byte layout (scratch overlaid on W region) ----------------
#define O_AHI  0
#define O_ALO  (O_AHI + M_ROWS * SBB)          // 17408
#define O_WHI  (O_ALO + M_ROWS * SBB)          // 34816
#define O_WLO  (O_WHI + 128 * SBW)             // 69632
#define O_WEND (O_WLO + 128 * SBW)             // 104448
// part/fin overlay the (dead-between-GEMMs) W-hi region
#define O_PART O_WHI
#define PART_STRIDE 68
#define O_FIN  (O_PART + M_ROWS * PART_STRIDE * 4)   // 34816+17408=52224 (< O_WLO+... inside W)
#define FIN_STRIDE 20
#define O_LN   O_WEND                           // 104448, 64*12*4 = 3072
#define LN_STRIDE 12
#define O_VEC  (O_LN + M_ROWS * LN_STRIDE * 4)  // 107520
#define VF_BIAS 0
#define VF_G    (VF_BIAS + 4 * 128)
#define VF_BE   (VF_G + 3 * 128)
#define VF_BC   (VF_BE + 3 * 128)
#define VF_TOT  (VF_BC + 16)
#define SMEM_TOTAL (O_VEC + VF_TOT * 4)         // 112704 B -> 2 CTAs/SM

// ---------------- f32x2 helpers ----------------
__device__ __forceinline__ ull pack2(float lo, float hi) {
    ull r; asm("mov.b64 %0, {%1, %2};" : "=l"(r) : "f"(lo), "f"(hi)); return r;
}
__device__ __forceinline__ void unpack2(ull v, float& lo, float& hi) {
    asm("mov.b64 {%0, %1}, %2;" : "=f"(lo), "=f"(hi) : "l"(v));
}
__device__ __forceinline__ ull fma2(ull a, ull b, ull c) {
    ull d; asm("fma.rn.f32x2 %0, %1, %2, %3;" : "=l"(d) : "l"(a), "l"(b), "l"(c)); return d;
}
__device__ __forceinline__ ull add2(ull a, ull b) {
    ull d; asm("add.rn.f32x2 %0, %1, %2;" : "=l"(d) : "l"(a), "l"(b)); return d;
}
__device__ __forceinline__ ull mul2(ull a, ull b) {
    ull d; asm("mul.rn.f32x2 %0, %1, %2;" : "=l"(d) : "l"(a), "l"(b)); return d;
}

__device__ __forceinline__ uint32_t smem_u32(const void* p) {
    uint32_t a;
    asm("{ .reg .u64 t; cvta.to.shared.u64 t, %1; cvt.u32.u64 %0, t; }" : "=r"(a) : "l"(p));
    return a;
}

// ---------------- tensor-core primitives ----------------
#define LDSM4(r, addr)                                                          \
    asm volatile("ldmatrix.sync.aligned.m8n8.x4.shared.b16 {%0,%1,%2,%3}, [%4];" \
        : "=r"((r)[0]), "=r"((r)[1]), "=r"((r)[2]), "=r"((r)[3]) : "r"(addr))
#define LDSM4T(r, addr)                                                         \
    asm volatile("ldmatrix.sync.aligned.m8n8.x4.trans.shared.b16 {%0,%1,%2,%3}, [%4];" \
        : "=r"((r)[0]), "=r"((r)[1]), "=r"((r)[2]), "=r"((r)[3]) : "r"(addr))

#define MMA_BF16(d, a, b0, b1)                                                  \
    asm volatile("mma.sync.aligned.m16n8k16.row.col.f32.bf16.bf16.f32 "         \
        "{%0,%1,%2,%3}, {%4,%5,%6,%7}, {%8,%9}, {%0,%1,%2,%3};"                 \
        : "+f"((d)[0]), "+f"((d)[1]), "+f"((d)[2]), "+f"((d)[3])                \
        : "r"((a)[0]), "r"((a)[1]), "r"((a)[2]), "r"((a)[3]), "r"(b0), "r"(b1))

// group barrier: 4 n-warps (128 threads) sharing one 32-row m-group
#define BARG(g) asm volatile("bar.sync %0, %1;" :: "r"((g) + 1), "r"(128) : "memory")

// ---------------- bf16 split ----------------
union BU { __nv_bfloat162 b; uint32_t u; };
__device__ __forceinline__ void split2(float v0, float v1, uint32_t& hi2, uint32_t& lo2) {
    BU h; h.b = __floats2bfloat162_rn(v0, v1);
    float r0 = v0 - __bfloat162float(__low2bfloat16(h.b));
    float r1 = v1 - __bfloat162float(__high2bfloat16(h.b));
    BU l; l.b = __floats2bfloat162_rn(r0, r1);
    hi2 = h.u; lo2 = l.u;
}

__device__ __forceinline__ float tanh_fast(float x) {
    float y; asm("tanh.approx.f32 %0, %1;" : "=f"(y) : "f"(x)); return y;
}

__device__ __forceinline__ void mom_acc(ull sm2[KT2], ull mm2[KT2], float u, float h) {
    float uu = u * u;
    ull pwp = pack2(1.0f, u);
    ull u2d = pack2(uu, uu);
    ull h2  = pack2(h, h);
#pragma unroll
    for (int p = 0; p < KT2; p++) {
        sm2[p] = add2(sm2[p], pwp);
        mm2[p] = fma2(pwp, h2, mm2[p]);
        if (p < KT2 - 1) pwp = mul2(pwp, u2d);
    }
}

// 3-pass bf16-split GEMM: D[64x128] = A[64x128] @ W[128x128]. Per-warp 32x32.
__device__ __forceinline__ void mma_gemm(uint32_t sb, uint32_t aOff, uint32_t bOffT,
                                         float d[2][4][4]) {
#pragma unroll
    for (int mi = 0; mi < 2; mi++)
#pragma unroll
        for (int na = 0; na < 4; na++)
#pragma unroll
            for (int e = 0; e < 4; e++) d[mi][na][e] = 0.f;

    const uint32_t aHi = sb + O_AHI + aOff, aLo = sb + O_ALO + aOff;
    const uint32_t bHi = sb + O_WHI + bOffT, bLo = sb + O_WLO + bOffT;
#pragma unroll
    for (int kk = 0; kk < 8; kk++) {
        uint32_t ko  = kk * 32;
        uint32_t bko = kk * 16 * SBW;
        uint32_t ahi0[4], ahi1[4], alo0[4], alo1[4];
        uint32_t bhi0[4], bhi1[4], blo0[4], blo1[4];
        LDSM4(ahi0, aHi + ko);
        LDSM4(ahi1, aHi + 16 * SBB + ko);
        LDSM4(alo0, aLo + ko);
        LDSM4(alo1, aLo + 16 * SBB + ko);
        LDSM4T(bhi0, bHi + bko);
        LDSM4T(bhi1, bHi + bko + 32);
        LDSM4T(blo0, bLo + bko);
        LDSM4T(blo1, bLo + bko + 32);
#pragma unroll
        for (int mi = 0; mi < 2; mi++) {
            uint32_t* ah = mi ? ahi1 : ahi0;
            uint32_t* al = mi ? alo1 : alo0;
#pragma unroll
            for (int np = 0; np < 2; np++) {
                uint32_t* bh = np ? bhi1 : bhi0;
                uint32_t* bl = np ? blo1 : blo0;
#pragma unroll
                for (int ns = 0; ns < 2; ns++) {
                    float* dd = d[mi][np * 2 + ns];
                    MMA_BF16(dd, ah, bh[2 * ns], bh[2 * ns + 1]);
                    MMA_BF16(dd, ah, bl[2 * ns], bl[2 * ns + 1]);
                    MMA_BF16(dd, al, bh[2 * ns], bh[2 * ns + 1]);
                }
            }
        }
    }
}

__device__ __forceinline__ void stage_w(char* smem, const float* __restrict__ Wg, int tid) {
#pragma unroll
    for (int it = 0; it < 32; it++) {
        int idx = tid + it * THREADS;          // 8192 = 128 k-rows x 64 n-pairs
        int k = idx >> 6, np = idx & 63;
        float2 w = *(const float2*)(Wg + (size_t)k * H + 2 * np);
        uint32_t hi2, lo2; split2(w.x, w.y, hi2, lo2);
        uint32_t off = (uint32_t)k * SBW + (uint32_t)np * 4;
        *(uint32_t*)(smem + O_WHI + off) = hi2;
        *(uint32_t*)(smem + O_WLO + off) = lo2;
    }
}

__global__ void __launch_bounds__(THREADS, 2)
simple_attention_kernel(const float* __restrict__ x,
                        const float* __restrict__ W_in,
                        const float* __restrict__ b_in,
                        const float* __restrict__ W_att,
                        const float* __restrict__ b_att,
                        const float* __restrict__ gamma,
                        const float* __restrict__ beta,
                        const float* __restrict__ W_c,
                        const float* __restrict__ b_c,
                        float* __restrict__ out)
{
    extern __shared__ char smem[];
    const uint32_t sb = smem_u32(smem);
    float* part = (float*)(smem + O_PART);
    float* fin  = (float*)(smem + O_FIN);
    float* lns  = (float*)(smem + O_LN);
    float* vec  = (float*)(smem + O_VEC);

    const int tid  = threadIdx.x;
    const int wid  = tid >> 5, lane = tid & 31;
    const int base = blockIdx.x * M_ROWS;
    const int gq = wid & 1;              // m-row group (2 groups x 32 rows)
    const int m0 = gq * 32;
    const int wc = wid >> 1;             // n-warp 0..3
    const int n0 = wc * 32;
    const int tg = (wc << 5) + lane;     // index within the 128-thread group

    const uint32_t aOff = (uint32_t)(m0 + (lane & 15)) * SBB + ((uint32_t)(lane >> 4) << 4);
    const uint32_t bOffT = (uint32_t)(((lane >> 3) & 1) * 8 + (lane & 7)) * SBW
                         + ((uint32_t)(n0 + ((lane >> 4) << 3)) << 1);

    const int rBase = m0 + (lane >> 2);
    const int cBase = n0 + (lane & 3) * 2;

    const float invf[KT] = {1.0f, 1.0f, 0.5f, 1.6666666667e-1f, 4.1666666667e-2f,
                            8.3333333333e-3f, 1.3888888889e-3f, 1.9841269841e-4f};

    // ---------------- initial staging ----------------
#pragma unroll
    for (int it = 0; it < 16; it++) {
        int idx = tid + it * THREADS;          // 4096 = 64 rows x 64 col-pairs
        int row = idx >> 6, kp = idx & 63;
        float2 v = *(const float2*)(x + (size_t)(base + row) * H + 2 * kp);
        uint32_t hi2, lo2; split2(v.x, v.y, hi2, lo2);
        uint32_t off = (uint32_t)row * SBB + (uint32_t)kp * 4;
        *(uint32_t*)(smem + O_AHI + off) = hi2;
        *(uint32_t*)(smem + O_ALO + off) = lo2;
    }
    stage_w(smem, W_in, tid);
    if (tid < 128) vec[VF_BIAS + tid] = b_in[tid];
    for (int i = tid; i < 3 * 128; i += THREADS) {
        vec[VF_BIAS + 128 + i] = b_att[i];
        vec[VF_G + i]  = gamma[i];
        vec[VF_BE + i] = beta[i];
    }
    if (tid < NC) vec[VF_BC + tid] = b_c[tid];
    __syncthreads();

    float d[2][4][4];
    float hreg[2][4][4];

    // ---------------- in-proj GEMM + epilogue (seeds hreg) ----------------
    mma_gemm(sb, aOff, bOffT, d);
    BARG(gq);                              // group's GEMM A-reads done before A writes
    {
        const float* sBias = vec + VF_BIAS;
#pragma unroll
        for (int mi = 0; mi < 2; mi++)
#pragma unroll
        for (int ri = 0; ri < 2; ri++) {
            int row = rBase + mi * 16 + ri * 8;
#pragma unroll
            for (int na = 0; na < 4; na++) {
                int col = cBase + na * 8;
                float v0 = d[mi][na][2 * ri]     + sBias[col];
                float v1 = d[mi][na][2 * ri + 1] + sBias[col + 1];
                hreg[mi][na][2 * ri]     = v0;
                hreg[mi][na][2 * ri + 1] = v1;
                uint32_t hi2, lo2; split2(v0, v1, hi2, lo2);
                uint32_t off = (uint32_t)row * SBB + (uint32_t)col * 2;
                *(uint32_t*)(smem + O_AHI + off) = hi2;
                *(uint32_t*)(smem + O_ALO + off) = lo2;
            }
        }
    }
    __syncthreads();                       // all W_in reads done
    stage_w(smem, W_att, tid);
    __syncthreads();

    // ---------------- attention layers ----------------
    for (int l = 0; l < NATT; l++) {
        const bool lastl = (l == NATT - 1);
        mma_gemm(sb, aOff, bOffT, d);
        __syncthreads();   // all W reads done; part may now overlay W-hi region

        const float* sBias = vec + VF_BIAS + 128 + l * 128;
        const float* sG    = vec + VF_G + l * 128;
        const float* sBe   = vec + VF_BE + l * 128;

        // ---- pass A: u = tanh(D+b); moments from hreg; quad-shfl; part ----
#pragma unroll
        for (int mi = 0; mi < 2; mi++)
#pragma unroll
        for (int ri = 0; ri < 2; ri++) {
            int row = rBase + mi * 16 + ri * 8;
            ull sm2[KT2], mm2[KT2];
#pragma unroll
            for (int p = 0; p < KT2; p++) { sm2[p] = 0ull; mm2[p] = 0ull; }
#pragma unroll
            for (int na = 0; na < 4; na++) {
                int col = cBase + na * 8;
                float u0 = tanh_fast(d[mi][na][2 * ri]     + sBias[col]);
                float u1 = tanh_fast(d[mi][na][2 * ri + 1] + sBias[col + 1]);
                d[mi][na][2 * ri]     = u0;
                d[mi][na][2 * ri + 1] = u1;
                mom_acc(sm2, mm2, u0, hreg[mi][na][2 * ri]);
                mom_acc(sm2, mm2, u1, hreg[mi][na][2 * ri + 1]);
            }
            float v16[16];
#pragma unroll
            for (int p = 0; p < KT2; p++) {
                unpack2(sm2[p], v16[2 * p], v16[2 * p + 1]);
                unpack2(mm2[p], v16[8 + 2 * p], v16[8 + 2 * p + 1]);
            }
#pragma unroll
            for (int k = 0; k < 16; k++) {
                v16[k] += __shfl_xor_sync(0xffffffffu, v16[k], 1);
                v16[k] += __shfl_xor_sync(0xffffffffu, v16[k], 2);
            }
            int j = lane & 3;
            *(float4*)&part[row * PART_STRIDE + wc * 16 + j * 4] =
                make_float4(v16[j * 4], v16[j * 4 + 1], v16[j * 4 + 2], v16[j * 4 + 3]);
        }
        BARG(gq);

        // ---- group reduce: part -> fin ----
        {
            int row = m0 + (tg >> 2), j = tg & 3;
            float4 s = *(const float4*)&part[row * PART_STRIDE + 0 * 16 + j * 4];
#pragma unroll
            for (int q = 1; q < 4; q++) {
                float4 t = *(const float4*)&part[row * PART_STRIDE + q * 16 + j * 4];
                s.x += t.x; s.y += t.y; s.z += t.z; s.w += t.w;
            }
            *(float4*)&fin[row * FIN_STRIDE + j * 4] = s;
        }
        BARG(gq);

        // ---- pass B: Horner, z in regs, LN partials ----
#pragma unroll
        for (int mi = 0; mi < 2; mi++)
#pragma unroll
        for (int ri = 0; ri < 2; ri++) {
            int row = rBase + mi * 16 + ri * 8;
            float4 f0 = *(const float4*)&fin[row * FIN_STRIDE + 0];
            float4 f1 = *(const float4*)&fin[row * FIN_STRIDE + 4];
            float4 f2 = *(const float4*)&fin[row * FIN_STRIDE + 8];
            float4 f3 = *(const float4*)&fin[row * FIN_STRIDE + 12];
            float smv[8] = {f0.x, f0.y, f0.z, f0.w, f1.x, f1.y, f1.z, f1.w};
            float mmv[8] = {f2.x, f2.y, f2.z, f2.w, f3.x, f3.y, f3.z, f3.w};
            ull pm[KT];
#pragma unroll
            for (int k = 0; k < KT; k++) pm[k] = pack2(mmv[k] * invf[k], smv[k] * invf[k]);

            float lsum = 0.f, lsq = 0.f;
#pragma unroll
            for (int na = 0; na < 4; na++) {
#pragma unroll
                for (int ci = 0; ci < 2; ci++) {
                    float u = d[mi][na][2 * ri + ci];
                    ull u2 = pack2(u, u);
                    ull nd = pm[KT - 1];
#pragma unroll
                    for (int k = KT - 2; k >= 0; k--) nd = fma2(nd, u2, pm[k]);
                    float num, den; unpack2(nd, num, den);
                    float z = hreg[mi][na][2 * ri + ci] + __fdividef(num, den);
                    d[mi][na][2 * ri + ci] = z;
                    lsum += z;
                    lsq = fmaf(z, z, lsq);
                }
            }
            lsum += __shfl_xor_sync(0xffffffffu, lsum, 1);
            lsum += __shfl_xor_sync(0xffffffffu, lsum, 2);
            lsq  += __shfl_xor_sync(0xffffffffu, lsq, 1);
            lsq  += __shfl_xor_sync(0xffffffffu, lsq, 2);
            if ((lane & 3) == 0)
                *(float2*)&lns[row * LN_STRIDE + wc * 2] = make_float2(lsum, lsq);
        }
        __syncthreads();   // fin/part reads done -> W region reusable; lns visible

        // ---- stage next W over scratch+W region (overlaps pass C) ----
        if (!lastl) stage_w(smem, W_att + (size_t)(l + 1) * H * H, tid);

        // ---- pass C: LN apply -> hreg + A tiles, or fused classifier ----
        if (!lastl) {
#pragma unroll
            for (int mi = 0; mi < 2; mi++)
#pragma unroll
            for (int ri = 0; ri < 2; ri++) {
                int row = rBase + mi * 16 + ri * 8;
                float tsum = 0.f, tsq = 0.f;
#pragma unroll
                for (int q = 0; q < 4; q++) {
                    float2 t = *(const float2*)&lns[row * LN_STRIDE + q * 2];
                    tsum += t.x; tsq += t.y;
                }
                float mu   = tsum * (1.f / H);
                float var  = tsq * (1.f / H) - mu * mu;
                float rinv = rsqrtf(var + EPS_LN);
#pragma unroll
                for (int na = 0; na < 4; na++) {
                    int col = cBase + na * 8;
                    float hn0 = fmaf((d[mi][na][2 * ri]     - mu) * rinv, sG[col],     sBe[col]);
                    float hn1 = fmaf((d[mi][na][2 * ri + 1] - mu) * rinv, sG[col + 1], sBe[col + 1]);
                    hreg[mi][na][2 * ri]     = hn0;
                    hreg[mi][na][2 * ri + 1] = hn1;
                    uint32_t hi2, lo2; split2(hn0, hn1, hi2, lo2);
                    uint32_t off = (uint32_t)row * SBB + (uint32_t)col * 2;
                    *(uint32_t*)(smem + O_AHI + off) = hi2;
                    *(uint32_t*)(smem + O_ALO + off) = lo2;
                }
            }
            __syncthreads();   // W staged + A written -> next GEMM
        } else {
#pragma unroll
            for (int mi = 0; mi < 2; mi++)
#pragma unroll
            for (int ri = 0; ri < 2; ri++) {
                int row = rBase + mi * 16 + ri * 8;
                float tsum = 0.f, tsq = 0.f;
#pragma unroll
                for (int q = 0; q < 4; q++) {
                    float2 t = *(const float2*)&lns[row * LN_STRIDE + q * 2];
                    tsum += t.x; tsq += t.y;
                }
                float mu   = tsum * (1.f / H);
                float var  = tsq * (1.f / H) - mu * mu;
                float rinv = rsqrtf(var + EPS_LN);
                float acc[NC];
#pragma unroll
                for (int c = 0; c < NC; c++) acc[c] = 0.f;
#pragma unroll
                for (int na = 0; na < 4; na++) {
                    int col = cBase + na * 8;
                    float hn0 = fmaf((d[mi][na][2 * ri]     - mu) * rinv, sG[col],     sBe[col]);
                    float hn1 = fmaf((d[mi][na][2 * ri + 1] - mu) * rinv, sG[col + 1], sBe[col + 1]);
#pragma unroll
                    for (int c = 0; c < NC; c++)
                        acc[c] += hn0 * __ldg(&W_c[col * NC + c])
                                + hn1 * __ldg(&W_c[(col + 1) * NC + c]);
                }
#pragma unroll
                for (int c = 0; c < NC; c++) {
                    acc[c] += __shfl_xor_sync(0xffffffffu, acc[c], 1);
                    acc[c] += __shfl_xor_sync(0xffffffffu, acc[c], 2);
                }
                if ((lane & 3) == 0) {
                    float* p = &part[row * PART_STRIDE + wc * 10];
#pragma unroll
                    for (int c = 0; c < NC; c += 2)
                        *(float2*)&p[c] = make_float2(acc[c], acc[c + 1]);
                }
            }
            BARG(gq);
            // threads 0..63 gather rows 0..63 (warp 0 -> group-0 rows, warp 1 -> group-1 rows)
            if (tid < M_ROWS) {
                float o[NC];
#pragma unroll
                for (int c = 0; c < NC; c++) o[c] = vec[VF_BC + c];
#pragma unroll
                for (int q = 0; q < 4; q++)
#pragma unroll
                    for (int c = 0; c < NC; c++)
                        o[c] += part[tid * PART_STRIDE + q * 10 + c];
                float* og = out + (size_t)(base + tid) * NC;
#pragma unroll
                for (int c = 0; c < NC; c += 2)
                    *(float2*)&og[c] = make_float2(o[c], o[c + 1]);
            }
        }
    }
}

extern "C" void kernel_launch(void* const* d_in, const int* in_sizes, int n_in,
                              void* d_out, int out_size)
{
    const float* x     = (const float*)d_in[0];
    const float* W_in  = (const float*)d_in[1];
    const float* b_in  = (const float*)d_in[2];
    const float* W_att = (const float*)d_in[3];
    const float* b_att = (const float*)d_in[4];
    const float* gam   = (const float*)d_in[5];
    const float* bet   = (const float*)d_in[6];
    const float* W_c   = (const float*)d_in[7];
    const float* b_c   = (const float*)d_in[8];

    cudaFuncSetAttribute(simple_attention_kernel,
                         cudaFuncAttributeMaxDynamicSharedMemorySize, SMEM_TOTAL);

    simple_attention_kernel<<<B_TOTAL / M_ROWS, THREADS, SMEM_TOTAL>>>(
        x, W_in, b_in, W_att, b_att, gam, bet, W_c, b_c, (float*)d_out);
}